// round 5
// baseline (speedup 1.0000x reference)
#include <cuda_runtime.h>
#include <math.h>

// ---------------------------------------------------------------------------
// Problem constants (from reference: B=8, N=8192, C=512, H=8, ws=64, FFN=2048)
// ---------------------------------------------------------------------------
#define MTOK 65536      // B*N tokens
#define CDIM 512
#define FDIM 2048
#define NWIN 1024       // MTOK / 64
#define NHEAD 8

// ---------------------------------------------------------------------------
// Scratch (device globals; no runtime allocation allowed)
// ---------------------------------------------------------------------------
__device__ float g_q  [(size_t)MTOK * CDIM];
__device__ float g_k  [(size_t)MTOK * CDIM];
__device__ float g_v  [(size_t)MTOK * CDIM];
__device__ float g_att[(size_t)MTOK * CDIM];
__device__ float g_h1 [(size_t)MTOK * CDIM];
__device__ float g_tmp[(size_t)MTOK * CDIM];
__device__ float g_ffn[(size_t)MTOK * FDIM];

// ---------------------------------------------------------------------------
// SGEMM: C[M,N] = A[M,K] @ B[K,N] + bias (+ optional exact GELU)
// 128x128 block tile, BK=16, 256 threads, 8x8 per-thread tile,
// register-prefetch double buffering (one __syncthreads per k-tile).
// All dims are multiples of the tile sizes for this problem (no bounds checks).
// ---------------------------------------------------------------------------
#define BM 128
#define BN 128
#define BK 16

template <int ACT>
__global__ __launch_bounds__(256, 2)
void sgemm_bias(const float* __restrict__ A, const float* __restrict__ B,
                const float* __restrict__ bias, float* __restrict__ C,
                int M, int N, int K)
{
    __shared__ float As[2][BK][BM];   // stored k-major (transposed)
    __shared__ float Bs[2][BK][BN];

    const int tid = threadIdx.x;
    const int m0  = blockIdx.y * BM;
    const int n0  = blockIdx.x * BN;

    const int tr = tid >> 4;          // 0..15  (row group)
    const int tc = tid & 15;          // 0..15  (col group)

    // A tile: 128 rows x 16 cols = 512 float4 -> 2 per thread
    const int arow = tid >> 2;        // 0..63
    const int acol = (tid & 3) << 2;  // 0,4,8,12
    // B tile: 16 rows x 128 cols = 512 float4 -> 2 per thread
    const int brow = tid >> 5;        // 0..7
    const int bcol = (tid & 31) << 2; // 0..124

    const float* Ap0 = A + (size_t)(m0 + arow)      * K + acol;
    const float* Ap1 = A + (size_t)(m0 + arow + 64) * K + acol;
    const float* Bp0 = B + (size_t)brow       * N + n0 + bcol;
    const float* Bp1 = B + (size_t)(brow + 8) * N + n0 + bcol;

    float acc[8][8];
    #pragma unroll
    for (int i = 0; i < 8; i++)
        #pragma unroll
        for (int j = 0; j < 8; j++) acc[i][j] = 0.0f;

    // --- preload tile 0 ---
    float4 a0 = *(const float4*)(Ap0);
    float4 a1 = *(const float4*)(Ap1);
    float4 b0 = *(const float4*)(Bp0);
    float4 b1 = *(const float4*)(Bp1);

    As[0][acol + 0][arow] = a0.x; As[0][acol + 1][arow] = a0.y;
    As[0][acol + 2][arow] = a0.z; As[0][acol + 3][arow] = a0.w;
    As[0][acol + 0][arow + 64] = a1.x; As[0][acol + 1][arow + 64] = a1.y;
    As[0][acol + 2][arow + 64] = a1.z; As[0][acol + 3][arow + 64] = a1.w;
    *(float4*)&Bs[0][brow][bcol]     = b0;
    *(float4*)&Bs[0][brow + 8][bcol] = b1;
    __syncthreads();

    const int nt = K / BK;
    int buf = 0;
    for (int t = 0; t < nt; ++t) {
        const bool has_next = (t + 1 < nt);
        if (has_next) {
            const size_t koff = (size_t)(t + 1) * BK;
            a0 = *(const float4*)(Ap0 + koff);
            a1 = *(const float4*)(Ap1 + koff);
            b0 = *(const float4*)(Bp0 + koff * N);
            b1 = *(const float4*)(Bp1 + koff * N);
        }

        #pragma unroll
        for (int k = 0; k < BK; ++k) {
            float ar[8], br[8];
            *(float4*)&ar[0] = *(const float4*)&As[buf][k][tr * 8];
            *(float4*)&ar[4] = *(const float4*)&As[buf][k][tr * 8 + 4];
            *(float4*)&br[0] = *(const float4*)&Bs[buf][k][tc * 8];
            *(float4*)&br[4] = *(const float4*)&Bs[buf][k][tc * 8 + 4];
            #pragma unroll
            for (int i = 0; i < 8; i++)
                #pragma unroll
                for (int j = 0; j < 8; j++)
                    acc[i][j] = fmaf(ar[i], br[j], acc[i][j]);
        }

        if (has_next) {
            const int nb = buf ^ 1;
            As[nb][acol + 0][arow] = a0.x; As[nb][acol + 1][arow] = a0.y;
            As[nb][acol + 2][arow] = a0.z; As[nb][acol + 3][arow] = a0.w;
            As[nb][acol + 0][arow + 64] = a1.x; As[nb][acol + 1][arow + 64] = a1.y;
            As[nb][acol + 2][arow + 64] = a1.z; As[nb][acol + 3][arow + 64] = a1.w;
            *(float4*)&Bs[nb][brow][bcol]     = b0;
            *(float4*)&Bs[nb][brow + 8][bcol] = b1;
            __syncthreads();
            buf = nb;
        }
    }

    // --- epilogue: bias (+ GELU), vectorized store ---
    float bj[8];
    #pragma unroll
    for (int j = 0; j < 8; j++) bj[j] = bias[n0 + tc * 8 + j];

    #pragma unroll
    for (int i = 0; i < 8; i++) {
        float v[8];
        #pragma unroll
        for (int j = 0; j < 8; j++) {
            float x = acc[i][j] + bj[j];
            if (ACT == 1)
                x = 0.5f * x * (1.0f + erff(x * 0.70710678118654752f));
            v[j] = x;
        }
        float* crow = C + (size_t)(m0 + tr * 8 + i) * N + n0 + tc * 8;
        *(float4*)(crow)     = make_float4(v[0], v[1], v[2], v[3]);
        *(float4*)(crow + 4) = make_float4(v[4], v[5], v[6], v[7]);
    }
}

// ---------------------------------------------------------------------------
// Windowed multi-head attention: one block per (head, window).
// 64x64 tiles in smem. S computed into registers (4x4/thread), softmax per
// row by one warp, then O = P @ V. Scale = 1/sqrt(64) = 0.125.
// ---------------------------------------------------------------------------
__global__ __launch_bounds__(256)
void attn_kernel(const float* __restrict__ Q, const float* __restrict__ K,
                 const float* __restrict__ V, float* __restrict__ O)
{
    __shared__ float Qs[64][65];   // Q, then P (softmax probs)
    __shared__ float Ks[64][65];   // K, then V

    const int h   = blockIdx.x;    // 0..7
    const int w   = blockIdx.y;    // 0..1023
    const int tid = threadIdx.x;
    const size_t base = (size_t)w * 64 * CDIM + (size_t)h * 64;

    // load Q, K tiles (1024 float4 each, 4 per thread)
    for (int i = tid; i < 1024; i += 256) {
        const int r = i >> 4;
        const int c = (i & 15) << 2;
        float4 qv = *(const float4*)(Q + base + (size_t)r * CDIM + c);
        float4 kv = *(const float4*)(K + base + (size_t)r * CDIM + c);
        Qs[r][c] = qv.x; Qs[r][c + 1] = qv.y; Qs[r][c + 2] = qv.z; Qs[r][c + 3] = qv.w;
        Ks[r][c] = kv.x; Ks[r][c + 1] = kv.y; Ks[r][c + 2] = kv.z; Ks[r][c + 3] = kv.w;
    }
    __syncthreads();

    const int r0 = (tid >> 4) << 2;   // 0,4,...,60
    const int c0 = (tid & 15) << 2;   // 0,4,...,60

    // S = Q K^T  (4x4 per thread)
    float s[4][4];
    #pragma unroll
    for (int i = 0; i < 4; i++)
        #pragma unroll
        for (int j = 0; j < 4; j++) s[i][j] = 0.0f;

    #pragma unroll 4
    for (int d = 0; d < 64; ++d) {
        const float q0 = Qs[r0][d], q1 = Qs[r0 + 1][d], q2 = Qs[r0 + 2][d], q3 = Qs[r0 + 3][d];
        const float k0 = Ks[c0][d], k1 = Ks[c0 + 1][d], k2 = Ks[c0 + 2][d], k3 = Ks[c0 + 3][d];
        s[0][0] = fmaf(q0, k0, s[0][0]); s[0][1] = fmaf(q0, k1, s[0][1]);
        s[0][2] = fmaf(q0, k2, s[0][2]); s[0][3] = fmaf(q0, k3, s[0][3]);
        s[1][0] = fmaf(q1, k0, s[1][0]); s[1][1] = fmaf(q1, k1, s[1][1]);
        s[1][2] = fmaf(q1, k2, s[1][2]); s[1][3] = fmaf(q1, k3, s[1][3]);
        s[2][0] = fmaf(q2, k0, s[2][0]); s[2][1] = fmaf(q2, k1, s[2][1]);
        s[2][2] = fmaf(q2, k2, s[2][2]); s[2][3] = fmaf(q2, k3, s[2][3]);
        s[3][0] = fmaf(q3, k0, s[3][0]); s[3][1] = fmaf(q3, k1, s[3][1]);
        s[3][2] = fmaf(q3, k2, s[3][2]); s[3][3] = fmaf(q3, k3, s[3][3]);
    }
    __syncthreads();   // everyone done reading Qs/Ks

    // store scaled S over Qs; load V over Ks
    #pragma unroll
    for (int i = 0; i < 4; i++)
        #pragma unroll
        for (int j = 0; j < 4; j++)
            Qs[r0 + i][c0 + j] = s[i][j] * 0.125f;

    for (int i = tid; i < 1024; i += 256) {
        const int r = i >> 4;
        const int c = (i & 15) << 2;
        float4 vv = *(const float4*)(V + base + (size_t)r * CDIM + c);
        Ks[r][c] = vv.x; Ks[r][c + 1] = vv.y; Ks[r][c + 2] = vv.z; Ks[r][c + 3] = vv.w;
    }
    __syncthreads();

    // softmax: each warp handles 8 rows, 2 elements per lane
    const int warp = tid >> 5, lane = tid & 31;
    #pragma unroll
    for (int rr = 0; rr < 8; rr++) {
        const int row = warp * 8 + rr;
        float a = Qs[row][lane];
        float b = Qs[row][lane + 32];
        float mx = fmaxf(a, b);
        #pragma unroll
        for (int o = 16; o > 0; o >>= 1)
            mx = fmaxf(mx, __shfl_xor_sync(0xffffffffu, mx, o));
        const float ea = expf(a - mx);
        const float eb = expf(b - mx);
        float sm = ea + eb;
        #pragma unroll
        for (int o = 16; o > 0; o >>= 1)
            sm += __shfl_xor_sync(0xffffffffu, sm, o);
        const float inv = 1.0f / sm;
        Qs[row][lane]      = ea * inv;
        Qs[row][lane + 32] = eb * inv;
    }
    __syncthreads();

    // O = P @ V  (4x4 per thread)
    float o4[4][4];
    #pragma unroll
    for (int i = 0; i < 4; i++)
        #pragma unroll
        for (int j = 0; j < 4; j++) o4[i][j] = 0.0f;

    #pragma unroll 4
    for (int d = 0; d < 64; ++d) {
        const float p0 = Qs[r0][d], p1 = Qs[r0 + 1][d], p2 = Qs[r0 + 2][d], p3 = Qs[r0 + 3][d];
        const float v0 = Ks[d][c0], v1 = Ks[d][c0 + 1], v2 = Ks[d][c0 + 2], v3 = Ks[d][c0 + 3];
        o4[0][0] = fmaf(p0, v0, o4[0][0]); o4[0][1] = fmaf(p0, v1, o4[0][1]);
        o4[0][2] = fmaf(p0, v2, o4[0][2]); o4[0][3] = fmaf(p0, v3, o4[0][3]);
        o4[1][0] = fmaf(p1, v0, o4[1][0]); o4[1][1] = fmaf(p1, v1, o4[1][1]);
        o4[1][2] = fmaf(p1, v2, o4[1][2]); o4[1][3] = fmaf(p1, v3, o4[1][3]);
        o4[2][0] = fmaf(p2, v0, o4[2][0]); o4[2][1] = fmaf(p2, v1, o4[2][1]);
        o4[2][2] = fmaf(p2, v2, o4[2][2]); o4[2][3] = fmaf(p2, v3, o4[2][3]);
        o4[3][0] = fmaf(p3, v0, o4[3][0]); o4[3][1] = fmaf(p3, v1, o4[3][1]);
        o4[3][2] = fmaf(p3, v2, o4[3][2]); o4[3][3] = fmaf(p3, v3, o4[3][3]);
    }

    #pragma unroll
    for (int i = 0; i < 4; i++) {
        float* orow = O + base + (size_t)(r0 + i) * CDIM + c0;
        *(float4*)orow = make_float4(o4[i][0], o4[i][1], o4[i][2], o4[i][3]);
    }
}

// ---------------------------------------------------------------------------
// LayerNorm over C=512 of (a + b), one 256-thread block per row.
// out = gamma * (v - mu) / sqrt(var + 1e-12) + beta
// ---------------------------------------------------------------------------
__global__ __launch_bounds__(256)
void ln_residual(const float* __restrict__ a, const float* __restrict__ b,
                 const float* __restrict__ gamma, const float* __restrict__ beta,
                 float* __restrict__ out)
{
    const int row = blockIdx.x;
    const int t   = threadIdx.x;
    const size_t off = (size_t)row * CDIM;

    const float v0 = a[off + t]       + b[off + t];
    const float v1 = a[off + t + 256] + b[off + t + 256];

    float s = v0 + v1;
    float q = v0 * v0 + v1 * v1;
    #pragma unroll
    for (int o = 16; o > 0; o >>= 1) {
        s += __shfl_xor_sync(0xffffffffu, s, o);
        q += __shfl_xor_sync(0xffffffffu, q, o);
    }

    __shared__ float ss[8], qq[8];
    const int warp = t >> 5, lane = t & 31;
    if (lane == 0) { ss[warp] = s; qq[warp] = q; }
    __syncthreads();

    if (t < 32) {
        float s2 = (t < 8) ? ss[t] : 0.0f;
        float q2 = (t < 8) ? qq[t] : 0.0f;
        #pragma unroll
        for (int o = 4; o > 0; o >>= 1) {
            s2 += __shfl_xor_sync(0xffffffffu, s2, o);
            q2 += __shfl_xor_sync(0xffffffffu, q2, o);
        }
        if (t == 0) { ss[0] = s2; qq[0] = q2; }
    }
    __syncthreads();

    const float mu  = ss[0] * (1.0f / 512.0f);
    const float var = qq[0] * (1.0f / 512.0f) - mu * mu;
    const float inv = rsqrtf(var + 1e-12f);

    out[off + t]       = gamma[t]       * (v0 - mu) * inv + beta[t];
    out[off + t + 256] = gamma[t + 256] * (v1 - mu) * inv + beta[t + 256];
}

// ---------------------------------------------------------------------------
// Launch pipeline (graph-capturable: kernel launches only)
// ---------------------------------------------------------------------------
extern "C" void kernel_launch(void* const* d_in, const int* in_sizes, int n_in,
                              void* d_out, int out_size)
{
    const float* x      = (const float*)d_in[0];
    const float* wq     = (const float*)d_in[1];
    const float* bq     = (const float*)d_in[2];
    const float* wk     = (const float*)d_in[3];
    const float* bk     = (const float*)d_in[4];
    const float* wv     = (const float*)d_in[5];
    const float* bv     = (const float*)d_in[6];
    const float* wo     = (const float*)d_in[7];
    const float* bo     = (const float*)d_in[8];
    const float* gamma1 = (const float*)d_in[9];
    const float* beta1  = (const float*)d_in[10];
    const float* wfc1   = (const float*)d_in[11];
    const float* bfc1   = (const float*)d_in[12];
    const float* wfc2   = (const float*)d_in[13];
    const float* bfc2   = (const float*)d_in[14];
    const float* gamma2 = (const float*)d_in[15];
    const float* beta2  = (const float*)d_in[16];
    // d_in[17] = window_size (64), d_in[18] = n_head (8): fixed for this problem
    float* out = (float*)d_out;

    float *q, *k, *v, *att, *h1, *tmp, *ffn;
    cudaGetSymbolAddress((void**)&q,   g_q);
    cudaGetSymbolAddress((void**)&k,   g_k);
    cudaGetSymbolAddress((void**)&v,   g_v);
    cudaGetSymbolAddress((void**)&att, g_att);
    cudaGetSymbolAddress((void**)&h1,  g_h1);
    cudaGetSymbolAddress((void**)&tmp, g_tmp);
    cudaGetSymbolAddress((void**)&ffn, g_ffn);

    const dim3 blk(256);
    const dim3 gC(CDIM / BN, MTOK / BM);   // (4, 512)
    const dim3 gF(FDIM / BN, MTOK / BM);   // (16, 512)

    // QKV projections
    sgemm_bias<0><<<gC, blk>>>(x, wq, bq, q, MTOK, CDIM, CDIM);
    sgemm_bias<0><<<gC, blk>>>(x, wk, bk, k, MTOK, CDIM, CDIM);
    sgemm_bias<0><<<gC, blk>>>(x, wv, bv, v, MTOK, CDIM, CDIM);

    // windowed MHSA
    attn_kernel<<<dim3(NHEAD, NWIN), blk>>>(q, k, v, att);

    // output projection + residual + LN1
    sgemm_bias<0><<<gC, blk>>>(att, wo, bo, tmp, MTOK, CDIM, CDIM);
    ln_residual<<<MTOK, blk>>>(tmp, x, gamma1, beta1, h1);

    // MLP: fc1 (+exact GELU), fc2, residual + LN2 -> final output
    sgemm_bias<1><<<gF, blk>>>(h1, wfc1, bfc1, ffn, MTOK, FDIM, CDIM);
    sgemm_bias<0><<<gC, blk>>>(ffn, wfc2, bfc2, tmp, MTOK, CDIM, FDIM);
    ln_residual<<<MTOK, blk>>>(tmp, h1, gamma2, beta2, out);
}

// round 6
// speedup vs baseline: 2.3007x; 2.3007x over previous
#include <cuda_runtime.h>
#include <math.h>

// ---------------------------------------------------------------------------
// Problem constants (B=8, N=8192, C=512, H=8, ws=64, FFN=2048)
// ---------------------------------------------------------------------------
#define MTOK 65536      // B*N tokens
#define CDIM 512
#define FDIM 2048
#define NWIN 1024       // MTOK / 64
#define NHEAD 8

// ---------------------------------------------------------------------------
// Scratch (device globals; no runtime allocation allowed)
// ---------------------------------------------------------------------------
__device__ float g_q  [(size_t)MTOK * CDIM];
__device__ float g_k  [(size_t)MTOK * CDIM];
__device__ float g_v  [(size_t)MTOK * CDIM];
__device__ float g_att[(size_t)MTOK * CDIM];
__device__ float g_h1 [(size_t)MTOK * CDIM];
__device__ float g_tmp[(size_t)MTOK * CDIM];
__device__ float g_ffn[(size_t)MTOK * FDIM];

// ---------------------------------------------------------------------------
// tf32 helpers
// ---------------------------------------------------------------------------
__device__ __forceinline__ float tf32_rna(float x) {
    unsigned u;
    asm("cvt.rna.tf32.f32 %0, %1;" : "=r"(u) : "f"(x));
    return __uint_as_float(u);
}

__device__ __forceinline__ void mma_tf32(float c[4], const unsigned a[4],
                                         const unsigned b[2]) {
    asm volatile(
        "mma.sync.aligned.m16n8k8.row.col.f32.tf32.tf32.f32 "
        "{%0,%1,%2,%3},{%4,%5,%6,%7},{%8,%9},{%0,%1,%2,%3};"
        : "+f"(c[0]), "+f"(c[1]), "+f"(c[2]), "+f"(c[3])
        : "r"(a[0]), "r"(a[1]), "r"(a[2]), "r"(a[3]),
          "r"(b[0]), "r"(b[1]));
}

// ---------------------------------------------------------------------------
// GEMM (tf32 tensor cores): C[M,N] = A[M,K] @ B[K,N] + bias (+ exact GELU)
// CTA tile 128x256, BK=16, 256 threads (8 warps 2x4), warp tile 64x64,
// m16n8k8.tf32 fragments. Double-buffered smem with register prefetch.
// Smem pitches PA=136 / PB=264 make ALL fragment LDS and tile STS
// conflict-free (bank = 8k + m; (tig,gid) -> 8*tig+gid covers 32 banks).
// Operands are RNA-rounded to tf32 at STS time; accumulation is fp32.
// M%128==0, N%256==0, K%16==0 hold for all five GEMMs here.
// ---------------------------------------------------------------------------
#define PA 136
#define PB 264
#define GEMM_SMEM ((2*16*PA + 2*16*PB) * (int)sizeof(float))   // 51200 B

template <int ACT>
__global__ __launch_bounds__(256, 1)
void gemm_tf32(const float* __restrict__ A, const float* __restrict__ B,
               const float* __restrict__ bias, float* __restrict__ C,
               int M, int N, int K)
{
    extern __shared__ float smem[];
    float* As = smem;                 // [2][16][PA]
    float* Bs = smem + 2 * 16 * PA;   // [2][16][PB]

    const int tid = threadIdx.x;
    const int m0  = blockIdx.y * 128;
    const int n0  = blockIdx.x * 256;

    // --- A loader: warp lanes cover 32 distinct rows -> conflict-free STS ---
    const int arow = tid & 63;              // 0..63 (and +64)
    const int acol = (tid >> 6) << 2;       // 0,4,8,12
    // --- B loader: 16x256 tile, vector stores, conflict-free ---
    const int brow = tid >> 6;              // 0..3 (and +4,+8,+12)
    const int bcol = (tid & 63) << 2;       // 0..252

    const float* Ap0 = A + (size_t)(m0 + arow)      * K + acol;
    const float* Ap1 = A + (size_t)(m0 + arow + 64) * K + acol;
    const float* Bp  = B + (size_t)brow * N + n0 + bcol;

    // --- warp/fragment indices ---
    const int lane = tid & 31;
    const int gid  = lane >> 2;             // 0..7
    const int tig  = lane & 3;              // 0..3
    const int wid  = tid >> 5;
    const int wm0  = (wid & 1) << 6;        // warp m offset: 0/64
    const int wn0  = (wid >> 1) << 6;       // warp n offset: 0/64/128/192

    float acc[4][8][4];
    #pragma unroll
    for (int i = 0; i < 4; i++)
        #pragma unroll
        for (int j = 0; j < 8; j++) {
            acc[i][j][0] = 0.f; acc[i][j][1] = 0.f;
            acc[i][j][2] = 0.f; acc[i][j][3] = 0.f;
        }

    // --- preload tile 0 ---
    float4 a0 = *(const float4*)(Ap0);
    float4 a1 = *(const float4*)(Ap1);
    float4 b0 = *(const float4*)(Bp);
    float4 b1 = *(const float4*)(Bp + (size_t)4  * N);
    float4 b2 = *(const float4*)(Bp + (size_t)8  * N);
    float4 b3 = *(const float4*)(Bp + (size_t)12 * N);

    {
        float* Ad = As + (size_t)acol * PA;
        Ad[0 * PA + arow] = tf32_rna(a0.x); Ad[1 * PA + arow] = tf32_rna(a0.y);
        Ad[2 * PA + arow] = tf32_rna(a0.z); Ad[3 * PA + arow] = tf32_rna(a0.w);
        Ad[0 * PA + arow + 64] = tf32_rna(a1.x); Ad[1 * PA + arow + 64] = tf32_rna(a1.y);
        Ad[2 * PA + arow + 64] = tf32_rna(a1.z); Ad[3 * PA + arow + 64] = tf32_rna(a1.w);
        float4 t;
        t = make_float4(tf32_rna(b0.x), tf32_rna(b0.y), tf32_rna(b0.z), tf32_rna(b0.w));
        *(float4*)&Bs[(brow +  0) * PB + bcol] = t;
        t = make_float4(tf32_rna(b1.x), tf32_rna(b1.y), tf32_rna(b1.z), tf32_rna(b1.w));
        *(float4*)&Bs[(brow +  4) * PB + bcol] = t;
        t = make_float4(tf32_rna(b2.x), tf32_rna(b2.y), tf32_rna(b2.z), tf32_rna(b2.w));
        *(float4*)&Bs[(brow +  8) * PB + bcol] = t;
        t = make_float4(tf32_rna(b3.x), tf32_rna(b3.y), tf32_rna(b3.z), tf32_rna(b3.w));
        *(float4*)&Bs[(brow + 12) * PB + bcol] = t;
    }
    __syncthreads();

    const int KT = K >> 4;
    int buf = 0;
    for (int t = 0; t < KT; ++t) {
        const bool has_next = (t + 1 < KT);
        if (has_next) {
            const size_t ko = (size_t)(t + 1) << 4;
            a0 = *(const float4*)(Ap0 + ko);
            a1 = *(const float4*)(Ap1 + ko);
            const float* bp = Bp + ko * N;
            b0 = *(const float4*)(bp);
            b1 = *(const float4*)(bp + (size_t)4  * N);
            b2 = *(const float4*)(bp + (size_t)8  * N);
            b3 = *(const float4*)(bp + (size_t)12 * N);
        }

        // --- compute: 2 k-steps of 8 ---
        #pragma unroll
        for (int ks = 0; ks < 2; ++ks) {
            const float* Ab = As + (size_t)(buf * 16 + ks * 8 + tig) * PA;
            const float* Bb = Bs + (size_t)(buf * 16 + ks * 8 + tig) * PB;

            unsigned af[4][4];
            #pragma unroll
            for (int mt = 0; mt < 4; ++mt) {
                const int r = wm0 + mt * 16 + gid;
                af[mt][0] = __float_as_uint(Ab[r]);
                af[mt][1] = __float_as_uint(Ab[r + 8]);
                af[mt][2] = __float_as_uint(Ab[4 * PA + r]);
                af[mt][3] = __float_as_uint(Ab[4 * PA + r + 8]);
            }
            unsigned bf[8][2];
            #pragma unroll
            for (int nt = 0; nt < 8; ++nt) {
                const int c = wn0 + nt * 8 + gid;
                bf[nt][0] = __float_as_uint(Bb[c]);
                bf[nt][1] = __float_as_uint(Bb[4 * PB + c]);
            }
            #pragma unroll
            for (int mt = 0; mt < 4; ++mt)
                #pragma unroll
                for (int nt = 0; nt < 8; ++nt)
                    mma_tf32(acc[mt][nt], af[mt], bf[nt]);
        }

        if (has_next) {
            const int nb = buf ^ 1;
            float* Ad = As + (size_t)(nb * 16 + acol) * PA;
            Ad[0 * PA + arow] = tf32_rna(a0.x); Ad[1 * PA + arow] = tf32_rna(a0.y);
            Ad[2 * PA + arow] = tf32_rna(a0.z); Ad[3 * PA + arow] = tf32_rna(a0.w);
            Ad[0 * PA + arow + 64] = tf32_rna(a1.x); Ad[1 * PA + arow + 64] = tf32_rna(a1.y);
            Ad[2 * PA + arow + 64] = tf32_rna(a1.z); Ad[3 * PA + arow + 64] = tf32_rna(a1.w);
            float* Bd = Bs + (size_t)(nb * 16) * PB;
            float4 tt;
            tt = make_float4(tf32_rna(b0.x), tf32_rna(b0.y), tf32_rna(b0.z), tf32_rna(b0.w));
            *(float4*)&Bd[(brow +  0) * PB + bcol] = tt;
            tt = make_float4(tf32_rna(b1.x), tf32_rna(b1.y), tf32_rna(b1.z), tf32_rna(b1.w));
            *(float4*)&Bd[(brow +  4) * PB + bcol] = tt;
            tt = make_float4(tf32_rna(b2.x), tf32_rna(b2.y), tf32_rna(b2.z), tf32_rna(b2.w));
            *(float4*)&Bd[(brow +  8) * PB + bcol] = tt;
            tt = make_float4(tf32_rna(b3.x), tf32_rna(b3.y), tf32_rna(b3.z), tf32_rna(b3.w));
            *(float4*)&Bd[(brow + 12) * PB + bcol] = tt;
            __syncthreads();
            buf = nb;
        }
    }

    // --- epilogue: bias (+GELU), float2 stores in c-fragment layout ---
    #pragma unroll
    for (int mt = 0; mt < 4; ++mt) {
        const int r = m0 + wm0 + mt * 16 + gid;
        #pragma unroll
        for (int nt = 0; nt < 8; ++nt) {
            const int c = n0 + wn0 + nt * 8 + 2 * tig;
            const float bb0 = bias[c];
            const float bb1 = bias[c + 1];
            float v0 = acc[mt][nt][0] + bb0;
            float v1 = acc[mt][nt][1] + bb1;
            float v2 = acc[mt][nt][2] + bb0;
            float v3 = acc[mt][nt][3] + bb1;
            if (ACT == 1) {
                v0 = 0.5f * v0 * (1.0f + erff(v0 * 0.70710678118654752f));
                v1 = 0.5f * v1 * (1.0f + erff(v1 * 0.70710678118654752f));
                v2 = 0.5f * v2 * (1.0f + erff(v2 * 0.70710678118654752f));
                v3 = 0.5f * v3 * (1.0f + erff(v3 * 0.70710678118654752f));
            }
            *(float2*)&C[(size_t)r * N + c]       = make_float2(v0, v1);
            *(float2*)&C[(size_t)(r + 8) * N + c] = make_float2(v2, v3);
        }
    }
}

// ---------------------------------------------------------------------------
// Windowed multi-head attention: one block per (head, window). (unchanged)
// ---------------------------------------------------------------------------
__global__ __launch_bounds__(256)
void attn_kernel(const float* __restrict__ Q, const float* __restrict__ K,
                 const float* __restrict__ V, float* __restrict__ O)
{
    __shared__ float Qs[64][65];
    __shared__ float Ks[64][65];

    const int h   = blockIdx.x;
    const int w   = blockIdx.y;
    const int tid = threadIdx.x;
    const size_t base = (size_t)w * 64 * CDIM + (size_t)h * 64;

    for (int i = tid; i < 1024; i += 256) {
        const int r = i >> 4;
        const int c = (i & 15) << 2;
        float4 qv = *(const float4*)(Q + base + (size_t)r * CDIM + c);
        float4 kv = *(const float4*)(K + base + (size_t)r * CDIM + c);
        Qs[r][c] = qv.x; Qs[r][c + 1] = qv.y; Qs[r][c + 2] = qv.z; Qs[r][c + 3] = qv.w;
        Ks[r][c] = kv.x; Ks[r][c + 1] = kv.y; Ks[r][c + 2] = kv.z; Ks[r][c + 3] = kv.w;
    }
    __syncthreads();

    const int r0 = (tid >> 4) << 2;
    const int c0 = (tid & 15) << 2;

    float s[4][4];
    #pragma unroll
    for (int i = 0; i < 4; i++)
        #pragma unroll
        for (int j = 0; j < 4; j++) s[i][j] = 0.0f;

    #pragma unroll 4
    for (int d = 0; d < 64; ++d) {
        const float q0 = Qs[r0][d], q1 = Qs[r0 + 1][d], q2 = Qs[r0 + 2][d], q3 = Qs[r0 + 3][d];
        const float k0 = Ks[c0][d], k1 = Ks[c0 + 1][d], k2 = Ks[c0 + 2][d], k3 = Ks[c0 + 3][d];
        s[0][0] = fmaf(q0, k0, s[0][0]); s[0][1] = fmaf(q0, k1, s[0][1]);
        s[0][2] = fmaf(q0, k2, s[0][2]); s[0][3] = fmaf(q0, k3, s[0][3]);
        s[1][0] = fmaf(q1, k0, s[1][0]); s[1][1] = fmaf(q1, k1, s[1][1]);
        s[1][2] = fmaf(q1, k2, s[1][2]); s[1][3] = fmaf(q1, k3, s[1][3]);
        s[2][0] = fmaf(q2, k0, s[2][0]); s[2][1] = fmaf(q2, k1, s[2][1]);
        s[2][2] = fmaf(q2, k2, s[2][2]); s[2][3] = fmaf(q2, k3, s[2][3]);
        s[3][0] = fmaf(q3, k0, s[3][0]); s[3][1] = fmaf(q3, k1, s[3][1]);
        s[3][2] = fmaf(q3, k2, s[3][2]); s[3][3] = fmaf(q3, k3, s[3][3]);
    }
    __syncthreads();

    #pragma unroll
    for (int i = 0; i < 4; i++)
        #pragma unroll
        for (int j = 0; j < 4; j++)
            Qs[r0 + i][c0 + j] = s[i][j] * 0.125f;

    for (int i = tid; i < 1024; i += 256) {
        const int r = i >> 4;
        const int c = (i & 15) << 2;
        float4 vv = *(const float4*)(V + base + (size_t)r * CDIM + c);
        Ks[r][c] = vv.x; Ks[r][c + 1] = vv.y; Ks[r][c + 2] = vv.z; Ks[r][c + 3] = vv.w;
    }
    __syncthreads();

    const int warp = tid >> 5, lane = tid & 31;
    #pragma unroll
    for (int rr = 0; rr < 8; rr++) {
        const int row = warp * 8 + rr;
        float a = Qs[row][lane];
        float b = Qs[row][lane + 32];
        float mx = fmaxf(a, b);
        #pragma unroll
        for (int o = 16; o > 0; o >>= 1)
            mx = fmaxf(mx, __shfl_xor_sync(0xffffffffu, mx, o));
        const float ea = expf(a - mx);
        const float eb = expf(b - mx);
        float sm = ea + eb;
        #pragma unroll
        for (int o = 16; o > 0; o >>= 1)
            sm += __shfl_xor_sync(0xffffffffu, sm, o);
        const float inv = 1.0f / sm;
        Qs[row][lane]      = ea * inv;
        Qs[row][lane + 32] = eb * inv;
    }
    __syncthreads();

    float o4[4][4];
    #pragma unroll
    for (int i = 0; i < 4; i++)
        #pragma unroll
        for (int j = 0; j < 4; j++) o4[i][j] = 0.0f;

    #pragma unroll 4
    for (int d = 0; d < 64; ++d) {
        const float p0 = Qs[r0][d], p1 = Qs[r0 + 1][d], p2 = Qs[r0 + 2][d], p3 = Qs[r0 + 3][d];
        const float v0 = Ks[d][c0], v1 = Ks[d][c0 + 1], v2 = Ks[d][c0 + 2], v3 = Ks[d][c0 + 3];
        o4[0][0] = fmaf(p0, v0, o4[0][0]); o4[0][1] = fmaf(p0, v1, o4[0][1]);
        o4[0][2] = fmaf(p0, v2, o4[0][2]); o4[0][3] = fmaf(p0, v3, o4[0][3]);
        o4[1][0] = fmaf(p1, v0, o4[1][0]); o4[1][1] = fmaf(p1, v1, o4[1][1]);
        o4[1][2] = fmaf(p1, v2, o4[1][2]); o4[1][3] = fmaf(p1, v3, o4[1][3]);
        o4[2][0] = fmaf(p2, v0, o4[2][0]); o4[2][1] = fmaf(p2, v1, o4[2][1]);
        o4[2][2] = fmaf(p2, v2, o4[2][2]); o4[2][3] = fmaf(p2, v3, o4[2][3]);
        o4[3][0] = fmaf(p3, v0, o4[3][0]); o4[3][1] = fmaf(p3, v1, o4[3][1]);
        o4[3][2] = fmaf(p3, v2, o4[3][2]); o4[3][3] = fmaf(p3, v3, o4[3][3]);
    }

    #pragma unroll
    for (int i = 0; i < 4; i++) {
        float* orow = O + base + (size_t)(r0 + i) * CDIM + c0;
        *(float4*)orow = make_float4(o4[i][0], o4[i][1], o4[i][2], o4[i][3]);
    }
}

// ---------------------------------------------------------------------------
// LayerNorm over C=512 of (a + b), one 256-thread block per row. (unchanged)
// ---------------------------------------------------------------------------
__global__ __launch_bounds__(256)
void ln_residual(const float* __restrict__ a, const float* __restrict__ b,
                 const float* __restrict__ gamma, const float* __restrict__ beta,
                 float* __restrict__ out)
{
    const int row = blockIdx.x;
    const int t   = threadIdx.x;
    const size_t off = (size_t)row * CDIM;

    const float v0 = a[off + t]       + b[off + t];
    const float v1 = a[off + t + 256] + b[off + t + 256];

    float s = v0 + v1;
    float q = v0 * v0 + v1 * v1;
    #pragma unroll
    for (int o = 16; o > 0; o >>= 1) {
        s += __shfl_xor_sync(0xffffffffu, s, o);
        q += __shfl_xor_sync(0xffffffffu, q, o);
    }

    __shared__ float ss[8], qq[8];
    const int warp = t >> 5, lane = t & 31;
    if (lane == 0) { ss[warp] = s; qq[warp] = q; }
    __syncthreads();

    if (t < 32) {
        float s2 = (t < 8) ? ss[t] : 0.0f;
        float q2 = (t < 8) ? qq[t] : 0.0f;
        #pragma unroll
        for (int o = 4; o > 0; o >>= 1) {
            s2 += __shfl_xor_sync(0xffffffffu, s2, o);
            q2 += __shfl_xor_sync(0xffffffffu, q2, o);
        }
        if (t == 0) { ss[0] = s2; qq[0] = q2; }
    }
    __syncthreads();

    const float mu  = ss[0] * (1.0f / 512.0f);
    const float var = qq[0] * (1.0f / 512.0f) - mu * mu;
    const float inv = rsqrtf(var + 1e-12f);

    out[off + t]       = gamma[t]       * (v0 - mu) * inv + beta[t];
    out[off + t + 256] = gamma[t + 256] * (v1 - mu) * inv + beta[t + 256];
}

// ---------------------------------------------------------------------------
// Launch pipeline (graph-capturable: kernel launches only)
// ---------------------------------------------------------------------------
extern "C" void kernel_launch(void* const* d_in, const int* in_sizes, int n_in,
                              void* d_out, int out_size)
{
    const float* x      = (const float*)d_in[0];
    const float* wq     = (const float*)d_in[1];
    const float* bq     = (const float*)d_in[2];
    const float* wk     = (const float*)d_in[3];
    const float* bk     = (const float*)d_in[4];
    const float* wv     = (const float*)d_in[5];
    const float* bv     = (const float*)d_in[6];
    const float* wo     = (const float*)d_in[7];
    const float* bo     = (const float*)d_in[8];
    const float* gamma1 = (const float*)d_in[9];
    const float* beta1  = (const float*)d_in[10];
    const float* wfc1   = (const float*)d_in[11];
    const float* bfc1   = (const float*)d_in[12];
    const float* wfc2   = (const float*)d_in[13];
    const float* bfc2   = (const float*)d_in[14];
    const float* gamma2 = (const float*)d_in[15];
    const float* beta2  = (const float*)d_in[16];
    float* out = (float*)d_out;

    float *q, *k, *v, *att, *h1, *tmp, *ffn;
    cudaGetSymbolAddress((void**)&q,   g_q);
    cudaGetSymbolAddress((void**)&k,   g_k);
    cudaGetSymbolAddress((void**)&v,   g_v);
    cudaGetSymbolAddress((void**)&att, g_att);
    cudaGetSymbolAddress((void**)&h1,  g_h1);
    cudaGetSymbolAddress((void**)&tmp, g_tmp);
    cudaGetSymbolAddress((void**)&ffn, g_ffn);

    // >48KB dynamic smem opt-in (module state, not a stream op; capture-safe)
    cudaFuncSetAttribute(gemm_tf32<0>, cudaFuncAttributeMaxDynamicSharedMemorySize, GEMM_SMEM);
    cudaFuncSetAttribute(gemm_tf32<1>, cudaFuncAttributeMaxDynamicSharedMemorySize, GEMM_SMEM);

    const dim3 blk(256);
    const dim3 gC(CDIM / 256, MTOK / 128);   // (2, 512)
    const dim3 gF(FDIM / 256, MTOK / 128);   // (8, 512)

    // QKV projections (tf32 tensor cores)
    gemm_tf32<0><<<gC, blk, GEMM_SMEM>>>(x, wq, bq, q, MTOK, CDIM, CDIM);
    gemm_tf32<0><<<gC, blk, GEMM_SMEM>>>(x, wk, bk, k, MTOK, CDIM, CDIM);
    gemm_tf32<0><<<gC, blk, GEMM_SMEM>>>(x, wv, bv, v, MTOK, CDIM, CDIM);

    // windowed MHSA
    attn_kernel<<<dim3(NHEAD, NWIN), blk>>>(q, k, v, att);

    // output projection + residual + LN1
    gemm_tf32<0><<<gC, blk, GEMM_SMEM>>>(att, wo, bo, tmp, MTOK, CDIM, CDIM);
    ln_residual<<<MTOK, blk>>>(tmp, x, gamma1, beta1, h1);

    // MLP: fc1 (+exact GELU), fc2, residual + LN2 -> final output
    gemm_tf32<1><<<gF, blk, GEMM_SMEM>>>(h1, wfc1, bfc1, ffn, MTOK, FDIM, CDIM);
    gemm_tf32<0><<<gC, blk, GEMM_SMEM>>>(ffn, wfc2, bfc2, tmp, MTOK, CDIM, FDIM);
    ln_residual<<<MTOK, blk>>>(tmp, h1, gamma2, beta2, out);
}

// round 7
// speedup vs baseline: 2.3031x; 1.0011x over previous
#include <cuda_runtime.h>
#include <math.h>

// ---------------------------------------------------------------------------
// Problem constants (B=8, N=8192, C=512, H=8, ws=64, FFN=2048)
// ---------------------------------------------------------------------------
#define MTOK 65536      // B*N tokens
#define CDIM 512
#define FDIM 2048
#define NWIN 1024       // MTOK / 64
#define NHEAD 8

// ---------------------------------------------------------------------------
// Scratch (device globals; no runtime allocation allowed)
// ---------------------------------------------------------------------------
__device__ float g_q  [(size_t)MTOK * CDIM];
__device__ float g_k  [(size_t)MTOK * CDIM];
__device__ float g_v  [(size_t)MTOK * CDIM];
__device__ float g_att[(size_t)MTOK * CDIM];
__device__ float g_h1 [(size_t)MTOK * CDIM];
__device__ float g_tmp[(size_t)MTOK * CDIM];
__device__ float g_ffn[(size_t)MTOK * FDIM];

// ---------------------------------------------------------------------------
// tf32 helpers
// ---------------------------------------------------------------------------
__device__ __forceinline__ float tf32_rna(float x) {
    unsigned u;
    asm("cvt.rna.tf32.f32 %0, %1;" : "=r"(u) : "f"(x));
    return __uint_as_float(u);
}

__device__ __forceinline__ void mma_tf32(float c[4], const unsigned a[4],
                                         const unsigned b[2]) {
    asm volatile(
        "mma.sync.aligned.m16n8k8.row.col.f32.tf32.tf32.f32 "
        "{%0,%1,%2,%3},{%4,%5,%6,%7},{%8,%9},{%0,%1,%2,%3};"
        : "+f"(c[0]), "+f"(c[1]), "+f"(c[2]), "+f"(c[3])
        : "r"(a[0]), "r"(a[1]), "r"(a[2]), "r"(a[3]),
          "r"(b[0]), "r"(b[1]));
}

// ---------------------------------------------------------------------------
// GEMM (tf32 tensor cores): C[M,N] = A[M,K] @ B[K,N] + bias (+ exact GELU)
// CTA tile 128x256, BK=16, 256 threads (8 warps 2x4), warp tile 64x64,
// m16n8k8.tf32 fragments. Double-buffered smem with register prefetch.
// Smem pitches PA=136 / PB=264 make ALL fragment LDS and tile STS
// conflict-free (bank = 8k + m; (tig,gid) -> 8*tig+gid covers 32 banks).
// Operands are RNA-rounded to tf32 at STS time; accumulation is fp32.
// M%128==0, N%256==0, K%16==0 hold for all five GEMMs here.
// ---------------------------------------------------------------------------
#define PA 136
#define PB 264
#define GEMM_SMEM ((2*16*PA + 2*16*PB) * (int)sizeof(float))   // 51200 B

template <int ACT>
__global__ __launch_bounds__(256, 1)
void gemm_tf32(const float* __restrict__ A, const float* __restrict__ B,
               const float* __restrict__ bias, float* __restrict__ C,
               int M, int N, int K)
{
    extern __shared__ float smem[];
    float* As = smem;                 // [2][16][PA]
    float* Bs = smem + 2 * 16 * PA;   // [2][16][PB]

    const int tid = threadIdx.x;
    const int m0  = blockIdx.y * 128;
    const int n0  = blockIdx.x * 256;

    // --- A loader: warp lanes cover 32 distinct rows -> conflict-free STS ---
    const int arow = tid & 63;              // 0..63 (and +64)
    const int acol = (tid >> 6) << 2;       // 0,4,8,12
    // --- B loader: 16x256 tile, vector stores, conflict-free ---
    const int brow = tid >> 6;              // 0..3 (and +4,+8,+12)
    const int bcol = (tid & 63) << 2;       // 0..252

    const float* Ap0 = A + (size_t)(m0 + arow)      * K + acol;
    const float* Ap1 = A + (size_t)(m0 + arow + 64) * K + acol;
    const float* Bp  = B + (size_t)brow * N + n0 + bcol;

    // --- warp/fragment indices ---
    const int lane = tid & 31;
    const int gid  = lane >> 2;             // 0..7
    const int tig  = lane & 3;              // 0..3
    const int wid  = tid >> 5;
    const int wm0  = (wid & 1) << 6;        // warp m offset: 0/64
    const int wn0  = (wid >> 1) << 6;       // warp n offset: 0/64/128/192

    float acc[4][8][4];
    #pragma unroll
    for (int i = 0; i < 4; i++)
        #pragma unroll
        for (int j = 0; j < 8; j++) {
            acc[i][j][0] = 0.f; acc[i][j][1] = 0.f;
            acc[i][j][2] = 0.f; acc[i][j][3] = 0.f;
        }

    // --- preload tile 0 ---
    float4 a0 = *(const float4*)(Ap0);
    float4 a1 = *(const float4*)(Ap1);
    float4 b0 = *(const float4*)(Bp);
    float4 b1 = *(const float4*)(Bp + (size_t)4  * N);
    float4 b2 = *(const float4*)(Bp + (size_t)8  * N);
    float4 b3 = *(const float4*)(Bp + (size_t)12 * N);

    {
        float* Ad = As + (size_t)acol * PA;
        Ad[0 * PA + arow] = tf32_rna(a0.x); Ad[1 * PA + arow] = tf32_rna(a0.y);
        Ad[2 * PA + arow] = tf32_rna(a0.z); Ad[3 * PA + arow] = tf32_rna(a0.w);
        Ad[0 * PA + arow + 64] = tf32_rna(a1.x); Ad[1 * PA + arow + 64] = tf32_rna(a1.y);
        Ad[2 * PA + arow + 64] = tf32_rna(a1.z); Ad[3 * PA + arow + 64] = tf32_rna(a1.w);
        float4 t;
        t = make_float4(tf32_rna(b0.x), tf32_rna(b0.y), tf32_rna(b0.z), tf32_rna(b0.w));
        *(float4*)&Bs[(brow +  0) * PB + bcol] = t;
        t = make_float4(tf32_rna(b1.x), tf32_rna(b1.y), tf32_rna(b1.z), tf32_rna(b1.w));
        *(float4*)&Bs[(brow +  4) * PB + bcol] = t;
        t = make_float4(tf32_rna(b2.x), tf32_rna(b2.y), tf32_rna(b2.z), tf32_rna(b2.w));
        *(float4*)&Bs[(brow +  8) * PB + bcol] = t;
        t = make_float4(tf32_rna(b3.x), tf32_rna(b3.y), tf32_rna(b3.z), tf32_rna(b3.w));
        *(float4*)&Bs[(brow + 12) * PB + bcol] = t;
    }
    __syncthreads();

    const int KT = K >> 4;
    int buf = 0;
    for (int t = 0; t < KT; ++t) {
        const bool has_next = (t + 1 < KT);
        if (has_next) {
            const size_t ko = (size_t)(t + 1) << 4;
            a0 = *(const float4*)(Ap0 + ko);
            a1 = *(const float4*)(Ap1 + ko);
            const float* bp = Bp + ko * N;
            b0 = *(const float4*)(bp);
            b1 = *(const float4*)(bp + (size_t)4  * N);
            b2 = *(const float4*)(bp + (size_t)8  * N);
            b3 = *(const float4*)(bp + (size_t)12 * N);
        }

        // --- compute: 2 k-steps of 8 ---
        #pragma unroll
        for (int ks = 0; ks < 2; ++ks) {
            const float* Ab = As + (size_t)(buf * 16 + ks * 8 + tig) * PA;
            const float* Bb = Bs + (size_t)(buf * 16 + ks * 8 + tig) * PB;

            unsigned af[4][4];
            #pragma unroll
            for (int mt = 0; mt < 4; ++mt) {
                const int r = wm0 + mt * 16 + gid;
                af[mt][0] = __float_as_uint(Ab[r]);
                af[mt][1] = __float_as_uint(Ab[r + 8]);
                af[mt][2] = __float_as_uint(Ab[4 * PA + r]);
                af[mt][3] = __float_as_uint(Ab[4 * PA + r + 8]);
            }
            unsigned bf[8][2];
            #pragma unroll
            for (int nt = 0; nt < 8; ++nt) {
                const int c = wn0 + nt * 8 + gid;
                bf[nt][0] = __float_as_uint(Bb[c]);
                bf[nt][1] = __float_as_uint(Bb[4 * PB + c]);
            }
            #pragma unroll
            for (int mt = 0; mt < 4; ++mt)
                #pragma unroll
                for (int nt = 0; nt < 8; ++nt)
                    mma_tf32(acc[mt][nt], af[mt], bf[nt]);
        }

        if (has_next) {
            const int nb = buf ^ 1;
            float* Ad = As + (size_t)(nb * 16 + acol) * PA;
            Ad[0 * PA + arow] = tf32_rna(a0.x); Ad[1 * PA + arow] = tf32_rna(a0.y);
            Ad[2 * PA + arow] = tf32_rna(a0.z); Ad[3 * PA + arow] = tf32_rna(a0.w);
            Ad[0 * PA + arow + 64] = tf32_rna(a1.x); Ad[1 * PA + arow + 64] = tf32_rna(a1.y);
            Ad[2 * PA + arow + 64] = tf32_rna(a1.z); Ad[3 * PA + arow + 64] = tf32_rna(a1.w);
            float* Bd = Bs + (size_t)(nb * 16) * PB;
            float4 tt;
            tt = make_float4(tf32_rna(b0.x), tf32_rna(b0.y), tf32_rna(b0.z), tf32_rna(b0.w));
            *(float4*)&Bd[(brow +  0) * PB + bcol] = tt;
            tt = make_float4(tf32_rna(b1.x), tf32_rna(b1.y), tf32_rna(b1.z), tf32_rna(b1.w));
            *(float4*)&Bd[(brow +  4) * PB + bcol] = tt;
            tt = make_float4(tf32_rna(b2.x), tf32_rna(b2.y), tf32_rna(b2.z), tf32_rna(b2.w));
            *(float4*)&Bd[(brow +  8) * PB + bcol] = tt;
            tt = make_float4(tf32_rna(b3.x), tf32_rna(b3.y), tf32_rna(b3.z), tf32_rna(b3.w));
            *(float4*)&Bd[(brow + 12) * PB + bcol] = tt;
            __syncthreads();
            buf = nb;
        }
    }

    // --- epilogue: bias (+GELU), float2 stores in c-fragment layout ---
    #pragma unroll
    for (int mt = 0; mt < 4; ++mt) {
        const int r = m0 + wm0 + mt * 16 + gid;
        #pragma unroll
        for (int nt = 0; nt < 8; ++nt) {
            const int c = n0 + wn0 + nt * 8 + 2 * tig;
            const float bb0 = bias[c];
            const float bb1 = bias[c + 1];
            float v0 = acc[mt][nt][0] + bb0;
            float v1 = acc[mt][nt][1] + bb1;
            float v2 = acc[mt][nt][2] + bb0;
            float v3 = acc[mt][nt][3] + bb1;
            if (ACT == 1) {
                v0 = 0.5f * v0 * (1.0f + erff(v0 * 0.70710678118654752f));
                v1 = 0.5f * v1 * (1.0f + erff(v1 * 0.70710678118654752f));
                v2 = 0.5f * v2 * (1.0f + erff(v2 * 0.70710678118654752f));
                v3 = 0.5f * v3 * (1.0f + erff(v3 * 0.70710678118654752f));
            }
            *(float2*)&C[(size_t)r * N + c]       = make_float2(v0, v1);
            *(float2*)&C[(size_t)(r + 8) * N + c] = make_float2(v2, v3);
        }
    }
}

// ---------------------------------------------------------------------------
// Windowed multi-head attention: one block per (head, window). (unchanged)
// ---------------------------------------------------------------------------
__global__ __launch_bounds__(256)
void attn_kernel(const float* __restrict__ Q, const float* __restrict__ K,
                 const float* __restrict__ V, float* __restrict__ O)
{
    __shared__ float Qs[64][65];
    __shared__ float Ks[64][65];

    const int h   = blockIdx.x;
    const int w   = blockIdx.y;
    const int tid = threadIdx.x;
    const size_t base = (size_t)w * 64 * CDIM + (size_t)h * 64;

    for (int i = tid; i < 1024; i += 256) {
        const int r = i >> 4;
        const int c = (i & 15) << 2;
        float4 qv = *(const float4*)(Q + base + (size_t)r * CDIM + c);
        float4 kv = *(const float4*)(K + base + (size_t)r * CDIM + c);
        Qs[r][c] = qv.x; Qs[r][c + 1] = qv.y; Qs[r][c + 2] = qv.z; Qs[r][c + 3] = qv.w;
        Ks[r][c] = kv.x; Ks[r][c + 1] = kv.y; Ks[r][c + 2] = kv.z; Ks[r][c + 3] = kv.w;
    }
    __syncthreads();

    const int r0 = (tid >> 4) << 2;
    const int c0 = (tid & 15) << 2;

    float s[4][4];
    #pragma unroll
    for (int i = 0; i < 4; i++)
        #pragma unroll
        for (int j = 0; j < 4; j++) s[i][j] = 0.0f;

    #pragma unroll 4
    for (int d = 0; d < 64; ++d) {
        const float q0 = Qs[r0][d], q1 = Qs[r0 + 1][d], q2 = Qs[r0 + 2][d], q3 = Qs[r0 + 3][d];
        const float k0 = Ks[c0][d], k1 = Ks[c0 + 1][d], k2 = Ks[c0 + 2][d], k3 = Ks[c0 + 3][d];
        s[0][0] = fmaf(q0, k0, s[0][0]); s[0][1] = fmaf(q0, k1, s[0][1]);
        s[0][2] = fmaf(q0, k2, s[0][2]); s[0][3] = fmaf(q0, k3, s[0][3]);
        s[1][0] = fmaf(q1, k0, s[1][0]); s[1][1] = fmaf(q1, k1, s[1][1]);
        s[1][2] = fmaf(q1, k2, s[1][2]); s[1][3] = fmaf(q1, k3, s[1][3]);
        s[2][0] = fmaf(q2, k0, s[2][0]); s[2][1] = fmaf(q2, k1, s[2][1]);
        s[2][2] = fmaf(q2, k2, s[2][2]); s[2][3] = fmaf(q2, k3, s[2][3]);
        s[3][0] = fmaf(q3, k0, s[3][0]); s[3][1] = fmaf(q3, k1, s[3][1]);
        s[3][2] = fmaf(q3, k2, s[3][2]); s[3][3] = fmaf(q3, k3, s[3][3]);
    }
    __syncthreads();

    #pragma unroll
    for (int i = 0; i < 4; i++)
        #pragma unroll
        for (int j = 0; j < 4; j++)
            Qs[r0 + i][c0 + j] = s[i][j] * 0.125f;

    for (int i = tid; i < 1024; i += 256) {
        const int r = i >> 4;
        const int c = (i & 15) << 2;
        float4 vv = *(const float4*)(V + base + (size_t)r * CDIM + c);
        Ks[r][c] = vv.x; Ks[r][c + 1] = vv.y; Ks[r][c + 2] = vv.z; Ks[r][c + 3] = vv.w;
    }
    __syncthreads();

    const int warp = tid >> 5, lane = tid & 31;
    #pragma unroll
    for (int rr = 0; rr < 8; rr++) {
        const int row = warp * 8 + rr;
        float a = Qs[row][lane];
        float b = Qs[row][lane + 32];
        float mx = fmaxf(a, b);
        #pragma unroll
        for (int o = 16; o > 0; o >>= 1)
            mx = fmaxf(mx, __shfl_xor_sync(0xffffffffu, mx, o));
        const float ea = expf(a - mx);
        const float eb = expf(b - mx);
        float sm = ea + eb;
        #pragma unroll
        for (int o = 16; o > 0; o >>= 1)
            sm += __shfl_xor_sync(0xffffffffu, sm, o);
        const float inv = 1.0f / sm;
        Qs[row][lane]      = ea * inv;
        Qs[row][lane + 32] = eb * inv;
    }
    __syncthreads();

    float o4[4][4];
    #pragma unroll
    for (int i = 0; i < 4; i++)
        #pragma unroll
        for (int j = 0; j < 4; j++) o4[i][j] = 0.0f;

    #pragma unroll 4
    for (int d = 0; d < 64; ++d) {
        const float p0 = Qs[r0][d], p1 = Qs[r0 + 1][d], p2 = Qs[r0 + 2][d], p3 = Qs[r0 + 3][d];
        const float v0 = Ks[d][c0], v1 = Ks[d][c0 + 1], v2 = Ks[d][c0 + 2], v3 = Ks[d][c0 + 3];
        o4[0][0] = fmaf(p0, v0, o4[0][0]); o4[0][1] = fmaf(p0, v1, o4[0][1]);
        o4[0][2] = fmaf(p0, v2, o4[0][2]); o4[0][3] = fmaf(p0, v3, o4[0][3]);
        o4[1][0] = fmaf(p1, v0, o4[1][0]); o4[1][1] = fmaf(p1, v1, o4[1][1]);
        o4[1][2] = fmaf(p1, v2, o4[1][2]); o4[1][3] = fmaf(p1, v3, o4[1][3]);
        o4[2][0] = fmaf(p2, v0, o4[2][0]); o4[2][1] = fmaf(p2, v1, o4[2][1]);
        o4[2][2] = fmaf(p2, v2, o4[2][2]); o4[2][3] = fmaf(p2, v3, o4[2][3]);
        o4[3][0] = fmaf(p3, v0, o4[3][0]); o4[3][1] = fmaf(p3, v1, o4[3][1]);
        o4[3][2] = fmaf(p3, v2, o4[3][2]); o4[3][3] = fmaf(p3, v3, o4[3][3]);
    }

    #pragma unroll
    for (int i = 0; i < 4; i++) {
        float* orow = O + base + (size_t)(r0 + i) * CDIM + c0;
        *(float4*)orow = make_float4(o4[i][0], o4[i][1], o4[i][2], o4[i][3]);
    }
}

// ---------------------------------------------------------------------------
// LayerNorm over C=512 of (a + b), one 256-thread block per row. (unchanged)
// ---------------------------------------------------------------------------
__global__ __launch_bounds__(256)
void ln_residual(const float* __restrict__ a, const float* __restrict__ b,
                 const float* __restrict__ gamma, const float* __restrict__ beta,
                 float* __restrict__ out)
{
    const int row = blockIdx.x;
    const int t   = threadIdx.x;
    const size_t off = (size_t)row * CDIM;

    const float v0 = a[off + t]       + b[off + t];
    const float v1 = a[off + t + 256] + b[off + t + 256];

    float s = v0 + v1;
    float q = v0 * v0 + v1 * v1;
    #pragma unroll
    for (int o = 16; o > 0; o >>= 1) {
        s += __shfl_xor_sync(0xffffffffu, s, o);
        q += __shfl_xor_sync(0xffffffffu, q, o);
    }

    __shared__ float ss[8], qq[8];
    const int warp = t >> 5, lane = t & 31;
    if (lane == 0) { ss[warp] = s; qq[warp] = q; }
    __syncthreads();

    if (t < 32) {
        float s2 = (t < 8) ? ss[t] : 0.0f;
        float q2 = (t < 8) ? qq[t] : 0.0f;
        #pragma unroll
        for (int o = 4; o > 0; o >>= 1) {
            s2 += __shfl_xor_sync(0xffffffffu, s2, o);
            q2 += __shfl_xor_sync(0xffffffffu, q2, o);
        }
        if (t == 0) { ss[0] = s2; qq[0] = q2; }
    }
    __syncthreads();

    const float mu  = ss[0] * (1.0f / 512.0f);
    const float var = qq[0] * (1.0f / 512.0f) - mu * mu;
    const float inv = rsqrtf(var + 1e-12f);

    out[off + t]       = gamma[t]       * (v0 - mu) * inv + beta[t];
    out[off + t + 256] = gamma[t + 256] * (v1 - mu) * inv + beta[t + 256];
}

// ---------------------------------------------------------------------------
// Launch pipeline (graph-capturable: kernel launches only)
// ---------------------------------------------------------------------------
extern "C" void kernel_launch(void* const* d_in, const int* in_sizes, int n_in,
                              void* d_out, int out_size)
{
    const float* x      = (const float*)d_in[0];
    const float* wq     = (const float*)d_in[1];
    const float* bq     = (const float*)d_in[2];
    const float* wk     = (const float*)d_in[3];
    const float* bk     = (const float*)d_in[4];
    const float* wv     = (const float*)d_in[5];
    const float* bv     = (const float*)d_in[6];
    const float* wo     = (const float*)d_in[7];
    const float* bo     = (const float*)d_in[8];
    const float* gamma1 = (const float*)d_in[9];
    const float* beta1  = (const float*)d_in[10];
    const float* wfc1   = (const float*)d_in[11];
    const float* bfc1   = (const float*)d_in[12];
    const float* wfc2   = (const float*)d_in[13];
    const float* bfc2   = (const float*)d_in[14];
    const float* gamma2 = (const float*)d_in[15];
    const float* beta2  = (const float*)d_in[16];
    float* out = (float*)d_out;

    float *q, *k, *v, *att, *h1, *tmp, *ffn;
    cudaGetSymbolAddress((void**)&q,   g_q);
    cudaGetSymbolAddress((void**)&k,   g_k);
    cudaGetSymbolAddress((void**)&v,   g_v);
    cudaGetSymbolAddress((void**)&att, g_att);
    cudaGetSymbolAddress((void**)&h1,  g_h1);
    cudaGetSymbolAddress((void**)&tmp, g_tmp);
    cudaGetSymbolAddress((void**)&ffn, g_ffn);

    // >48KB dynamic smem opt-in (module state, not a stream op; capture-safe)
    cudaFuncSetAttribute(gemm_tf32<0>, cudaFuncAttributeMaxDynamicSharedMemorySize, GEMM_SMEM);
    cudaFuncSetAttribute(gemm_tf32<1>, cudaFuncAttributeMaxDynamicSharedMemorySize, GEMM_SMEM);

    const dim3 blk(256);
    const dim3 gC(CDIM / 256, MTOK / 128);   // (2, 512)
    const dim3 gF(FDIM / 256, MTOK / 128);   // (8, 512)

    // QKV projections (tf32 tensor cores)
    gemm_tf32<0><<<gC, blk, GEMM_SMEM>>>(x, wq, bq, q, MTOK, CDIM, CDIM);
    gemm_tf32<0><<<gC, blk, GEMM_SMEM>>>(x, wk, bk, k, MTOK, CDIM, CDIM);
    gemm_tf32<0><<<gC, blk, GEMM_SMEM>>>(x, wv, bv, v, MTOK, CDIM, CDIM);

    // windowed MHSA
    attn_kernel<<<dim3(NHEAD, NWIN), blk>>>(q, k, v, att);

    // output projection + residual + LN1
    gemm_tf32<0><<<gC, blk, GEMM_SMEM>>>(att, wo, bo, tmp, MTOK, CDIM, CDIM);
    ln_residual<<<MTOK, blk>>>(tmp, x, gamma1, beta1, h1);

    // MLP: fc1 (+exact GELU), fc2, residual + LN2 -> final output
    gemm_tf32<1><<<gF, blk, GEMM_SMEM>>>(h1, wfc1, bfc1, ffn, MTOK, FDIM, CDIM);
    gemm_tf32<0><<<gC, blk, GEMM_SMEM>>>(ffn, wfc2, bfc2, tmp, MTOK, CDIM, FDIM);
    ln_residual<<<MTOK, blk>>>(tmp, h1, gamma2, beta2, out);
}